// round 12
// baseline (speedup 1.0000x reference)
#include <cuda_runtime.h>
#include <cstdint>

// LoRA forward: out = (x @ B) @ A * 2
//   x: [8192, 4096] fp32, B: [4096, 16], A: [16, 4096], out: [8192, 4096]
//  lora_xb : FROZEN R7/R11 design (~35-40us): 64 rows/block, 2 rows/lane,
//            i-split x2, 4-stage cp.async pipeline (AT=32), 1 barrier/tile.
//  lora_out: NEW: 8 cols/thread (A slice 64 regs), 64 rows x 1024 cols per
//            block, 128 threads, grid 512 = single wave at occ 4.

#define ROWS_TOTAL 8192
#define IN_DIM     4096
#define OUT_DIM    4096
#define R_DIM      16

#define XB_SPLIT   2
#define XB_ISPAN   (IN_DIM / XB_SPLIT)     // 2048 i per block
#define XB_AT      32                       // i per tile
#define XB_NT      (XB_ISPAN / XB_AT)       // 64 tiles
#define XB_ROWS    64                       // rows per block (2 per lane)
#define XB_STAGES  4

typedef unsigned long long u64;

// partial xb: [split][row][8] u64, each u64 = (xb_{2j}, xb_{2j+1}), scaled by 2
__device__ u64 g_xbp[XB_SPLIT][ROWS_TOTAL][R_DIM / 2];

// ---------- packed f32x2 helpers ----------
__device__ __forceinline__ u64 pack2(float lo, float hi) {
    u64 r; asm("mov.b64 %0, {%1, %2};" : "=l"(r) : "f"(lo), "f"(hi)); return r;
}
__device__ __forceinline__ void unpack2(u64 v, float& lo, float& hi) {
    asm("mov.b64 {%0, %1}, %2;" : "=f"(lo), "=f"(hi) : "l"(v));
}
__device__ __forceinline__ void ffma2(u64& d, u64 a, u64 b) {
    asm("fma.rn.f32x2 %0, %1, %2, %0;" : "+l"(d) : "l"(a), "l"(b));
}
__device__ __forceinline__ void addf2(u64& d, u64 a, u64 b) {
    asm("add.rn.f32x2 %0, %1, %2;" : "=l"(d) : "l"(a), "l"(b));
}
__device__ __forceinline__ void mulf2(u64& d, u64 a, u64 b) {
    asm("mul.rn.f32x2 %0, %1, %2;" : "=l"(d) : "l"(a), "l"(b));
}

// ---------- cp.async helpers ----------
__device__ __forceinline__ uint32_t s2u(const void* p) {
    return (uint32_t)__cvta_generic_to_shared(p);
}
__device__ __forceinline__ void cp16(uint32_t dst, const void* src) {
    asm volatile("cp.async.cg.shared.global [%0], [%1], 16;"
                 :: "r"(dst), "l"(src) : "memory");
}
#define CP_COMMIT()  asm volatile("cp.async.commit_group;" ::: "memory")
#define CP_WAIT(N)   asm volatile("cp.async.wait_group %0;" :: "n"(N) : "memory")

// ---------- kernel A: partial xb (FROZEN) ----------
__global__ void __launch_bounds__(256, 3) lora_xb(const float* __restrict__ x,
                                                  const float* __restrict__ B) {
    __shared__ float xs[XB_STAGES][XB_ROWS][XB_AT];   // 4 x 8 KB
    __shared__ float bs[XB_STAGES][XB_AT][R_DIM];     // 4 x 2 KB

    const int tid   = threadIdx.x;
    const int wid   = tid >> 5;
    const int lane  = tid & 31;
    const int row0  = (blockIdx.x >> 1) * XB_ROWS;
    const int i0    = (blockIdx.x & 1) * XB_ISPAN;
    const int split = blockIdx.x & 1;

    const float4* xg = reinterpret_cast<const float4*>(x);
    const float4* Bg = reinterpret_cast<const float4*>(B);   // B row i = 4 float4

    auto stage = [&](int it, int buf) {
        float4* xs4 = reinterpret_cast<float4*>(&xs[buf][0][0]);   // [64][8]
        float4* bs4 = reinterpret_cast<float4*>(&bs[buf][0][0]);   // [128]
#pragma unroll
        for (int k = 0; k < 2; k++) {
            int f  = tid + k * 256;
            int rw = f >> 3;          // 0..63
            int c4 = f & 7;           // 0..7
            cp16(s2u(&xs4[rw * 8 + (c4 ^ (rw & 7))]),
                 &xg[(size_t)(row0 + rw) * (IN_DIM / 4) + (i0 >> 2) + it * (XB_AT / 4) + c4]);
        }
        if (tid < 128)
            cp16(s2u(&bs4[tid]), &Bg[(size_t)(i0 + it * XB_AT) * 4 + tid]);
        CP_COMMIT();
    };

    stage(0, 0);
    stage(1, 1);
    stage(2, 2);

    u64 acc[2][8];
#pragma unroll
    for (int s = 0; s < 2; s++)
#pragma unroll
        for (int j = 0; j < 8; j++) acc[s][j] = 0ull;

    for (int it = 0; it < XB_NT; it++) {
        const int buf = it % XB_STAGES;
        if      (it <= XB_NT - 3) { CP_WAIT(2); }
        else if (it == XB_NT - 2) { CP_WAIT(1); }
        else                      { CP_WAIT(0); }
        __syncthreads();
        if (it + 3 < XB_NT) stage(it + 3, (it + 3) % XB_STAGES);

        const float4*     xs4 = reinterpret_cast<const float4*>(&xs[buf][0][0]);
        const ulonglong2* bs2 = reinterpret_cast<const ulonglong2*>(&bs[buf][0][0]);

        float4 xq0 = xs4[lane * 8 + (wid ^ (lane & 7))];
        float4 xq1 = xs4[(lane + 32) * 8 + (wid ^ (lane & 7))];
        float xe0[4] = {xq0.x, xq0.y, xq0.z, xq0.w};
        float xe1[4] = {xq1.x, xq1.y, xq1.z, xq1.w};
#pragma unroll
        for (int e = 0; e < 4; e++) {
            const int il = wid * 4 + e;            // i within tile
            ulonglong2 b01 = bs2[il * 4 + 0];      // broadcast: r0..3
            ulonglong2 b23 = bs2[il * 4 + 1];      // r4..7
            ulonglong2 b45 = bs2[il * 4 + 2];      // r8..11
            ulonglong2 b67 = bs2[il * 4 + 3];      // r12..15
            u64 xx0 = pack2(xe0[e], xe0[e]);
            u64 xx1 = pack2(xe1[e], xe1[e]);
            ffma2(acc[0][0], xx0, b01.x);
            ffma2(acc[0][1], xx0, b01.y);
            ffma2(acc[0][2], xx0, b23.x);
            ffma2(acc[0][3], xx0, b23.y);
            ffma2(acc[0][4], xx0, b45.x);
            ffma2(acc[0][5], xx0, b45.y);
            ffma2(acc[0][6], xx0, b67.x);
            ffma2(acc[0][7], xx0, b67.y);
            ffma2(acc[1][0], xx1, b01.x);
            ffma2(acc[1][1], xx1, b01.y);
            ffma2(acc[1][2], xx1, b23.x);
            ffma2(acc[1][3], xx1, b23.y);
            ffma2(acc[1][4], xx1, b45.x);
            ffma2(acc[1][5], xx1, b45.y);
            ffma2(acc[1][6], xx1, b67.x);
            ffma2(acc[1][7], xx1, b67.y);
        }
    }
    __syncthreads();

    u64* red = reinterpret_cast<u64*>(&xs[0][0][0]);
#pragma unroll
    for (int s = 0; s < 2; s++)
#pragma unroll
        for (int j = 0; j < 8; j++)
            red[(wid * 32 + lane) * 16 + s * 8 + j] = acc[s][j];
    __syncthreads();

#pragma unroll
    for (int k = 0; k < 2; k++) {
        const int item = tid + k * 256;    // 0..511 -> (row, slot)
        const int row  = item >> 3;        // 0..63
        const int slot = item & 7;
        const int lrow = row & 31;
        const int rsel = row >> 5;
        u64 s = red[(0 * 32 + lrow) * 16 + rsel * 8 + slot];
#pragma unroll
        for (int w = 1; w < 8; w++)
            addf2(s, s, red[(w * 32 + lrow) * 16 + rsel * 8 + slot]);
        u64 two = pack2(2.0f, 2.0f);       // LoRA scale folded here
        mulf2(s, s, two);
        g_xbp[split][row0 + row][slot] = s;
    }
}

// ---------- kernel B: out = xb @ A (8 cols/thread, single wave) ----------
// 128 threads; block covers 64 rows x 1024 cols. A slice (16 r x 2 ulonglong2)
// in 64 regs; xb (sum of 2 splits) broadcast from smem via LDS.128.
// Grid = 128 rowblocks x 4 colblocks = 512 <= 592 slots at occ 4: one wave.
#define O_ROWS 64

__global__ void __launch_bounds__(128, 4) lora_out(const float* __restrict__ A,
                                                   float* __restrict__ out) {
    __shared__ u64 xbs[O_ROWS * R_DIM];   // 8 KB, entries packed (v,v)

    const int tid    = threadIdx.x;
    const int rowblk = blockIdx.x >> 2;
    const int colblk = blockIdx.x & 3;
    const int row0   = rowblk * O_ROWS;

    // fill xbs: 64 rows * 8 u64-slots = 512 -> 4 per thread; sum the 2 splits
    {
        const u64* g0 = &g_xbp[0][row0][0];
        const u64* g1 = &g_xbp[1][row0][0];
#pragma unroll
        for (int k = 0; k < 4; k++) {
            int j = tid + k * 128;            // j -> (row = j>>3, slot = j&7)
            u64 p;
            addf2(p, g0[j], g1[j]);
            float f0, f1;
            unpack2(p, f0, f1);
            int rw = j >> 3, slot = j & 7;
            xbs[rw * R_DIM + slot * 2 + 0] = pack2(f0, f0);
            xbs[rw * R_DIM + slot * 2 + 1] = pack2(f1, f1);
        }
    }
    __syncthreads();

    // A slice into registers: 16 r x 2 ulonglong2 (8 cols), coalesced
    const ulonglong2* Av = reinterpret_cast<const ulonglong2*>(A);  // [16][1024]
    const int cu = colblk * 256 + tid * 2;   // ulonglong2 index within a row
    ulonglong2 Ar0[R_DIM], Ar1[R_DIM];
#pragma unroll
    for (int rr = 0; rr < R_DIM; rr++) {
        Ar0[rr] = Av[(size_t)rr * (OUT_DIM / 4) + cu];
        Ar1[rr] = Av[(size_t)rr * (OUT_DIM / 4) + cu + 1];
    }

    ulonglong2* outv = reinterpret_cast<ulonglong2*>(out);
    const ulonglong2* xu = reinterpret_cast<const ulonglong2*>(xbs);

#pragma unroll 2
    for (int rw = 0; rw < O_ROWS; rw++) {
        u64 aE[4], aO[4];
#pragma unroll
        for (int c = 0; c < 4; c++) { aE[c] = 0ull; aO[c] = 0ull; }

#pragma unroll
        for (int q = 0; q < 8; q++) {
            ulonglong2 xq = xu[rw * 8 + q];   // bcast (xb_2q,xb_2q),(xb_2q+1,..)
            ulonglong2 e0 = Ar0[2 * q],     e1 = Ar1[2 * q];
            ulonglong2 o0 = Ar0[2 * q + 1], o1 = Ar1[2 * q + 1];
            ffma2(aE[0], xq.x, e0.x);
            ffma2(aE[1], xq.x, e0.y);
            ffma2(aE[2], xq.x, e1.x);
            ffma2(aE[3], xq.x, e1.y);
            ffma2(aO[0], xq.y, o0.x);
            ffma2(aO[1], xq.y, o0.y);
            ffma2(aO[2], xq.y, o1.x);
            ffma2(aO[3], xq.y, o1.y);
        }

        u64 s0, s1, s2, s3;
        addf2(s0, aE[0], aO[0]);
        addf2(s1, aE[1], aO[1]);
        addf2(s2, aE[2], aO[2]);
        addf2(s3, aE[3], aO[3]);
        ulonglong2 v0; v0.x = s0; v0.y = s1;
        ulonglong2 v1; v1.x = s2; v1.y = s3;
        const size_t ro = (size_t)(row0 + rw) * (OUT_DIM / 4);
        outv[ro + cu]     = v0;               // 2x STG.128, 32B/thread contig
        outv[ro + cu + 1] = v1;
    }
}

// ---------- launch ----------
extern "C" void kernel_launch(void* const* d_in, const int* in_sizes, int n_in,
                              void* d_out, int out_size) {
    const float* x  = (const float*)d_in[0];   // [4, 2048, 4096]
    const float* lA = (const float*)d_in[1];   // [16, 4096]
    const float* lB = (const float*)d_in[2];   // [4096, 16]
    float* out = (float*)d_out;

    lora_xb<<<(ROWS_TOTAL / XB_ROWS) * XB_SPLIT, 256>>>(x, lB);           // 256
    lora_out<<<(ROWS_TOTAL / O_ROWS) * (OUT_DIM / 1024), 128>>>(lA, out); // 512
}

// round 13
// speedup vs baseline: 1.5002x; 1.5002x over previous
#include <cuda_runtime.h>
#include <cstdint>

// LoRA forward: out = (x @ B) @ A * 2
//   x: [8192, 4096] fp32, B: [4096, 16], A: [16, 4096], out: [8192, 4096]
//  lora_xb : R7 pipeline, now occ 4 + i-split x4 (grid 512) for SM balance.
//  lora_out: R4 config EXACTLY (proven 30.6us), prologue sums 4 partials.

#define ROWS_TOTAL 8192
#define IN_DIM     4096
#define OUT_DIM    4096
#define R_DIM      16

#define XB_SPLIT   4
#define XB_ISPAN   (IN_DIM / XB_SPLIT)     // 1024 i per block
#define XB_AT      32                       // i per tile
#define XB_NT      (XB_ISPAN / XB_AT)       // 32 tiles
#define XB_ROWS    64                       // rows per block (2 per lane)
#define XB_STAGES  4

typedef unsigned long long u64;

// partial xb: [split][row][8] u64, each u64 = (xb_{2j}, xb_{2j+1}), scaled by 2
__device__ u64 g_xbp[XB_SPLIT][ROWS_TOTAL][R_DIM / 2];

// ---------- packed f32x2 helpers ----------
__device__ __forceinline__ u64 pack2(float lo, float hi) {
    u64 r; asm("mov.b64 %0, {%1, %2};" : "=l"(r) : "f"(lo), "f"(hi)); return r;
}
__device__ __forceinline__ void unpack2(u64 v, float& lo, float& hi) {
    asm("mov.b64 {%0, %1}, %2;" : "=f"(lo), "=f"(hi) : "l"(v));
}
__device__ __forceinline__ void ffma2(u64& d, u64 a, u64 b) {
    asm("fma.rn.f32x2 %0, %1, %2, %0;" : "+l"(d) : "l"(a), "l"(b));
}
__device__ __forceinline__ void addf2(u64& d, u64 a, u64 b) {
    asm("add.rn.f32x2 %0, %1, %2;" : "=l"(d) : "l"(a), "l"(b));
}
__device__ __forceinline__ void mulf2(u64& d, u64 a, u64 b) {
    asm("mul.rn.f32x2 %0, %1, %2;" : "=l"(d) : "l"(a), "l"(b));
}

// ---------- cp.async helpers ----------
__device__ __forceinline__ uint32_t s2u(const void* p) {
    return (uint32_t)__cvta_generic_to_shared(p);
}
__device__ __forceinline__ void cp16(uint32_t dst, const void* src) {
    asm volatile("cp.async.cg.shared.global [%0], [%1], 16;"
                 :: "r"(dst), "l"(src) : "memory");
}
#define CP_COMMIT()  asm volatile("cp.async.commit_group;" ::: "memory")
#define CP_WAIT(N)   asm volatile("cp.async.wait_group %0;" :: "n"(N) : "memory")

// ---------- kernel A: partial xb ----------
// 256 threads = 8 warps; lane covers rows {lane, lane+32}. Warp w covers
// i-subrange [w*4, w*4+4) of each 32-i tile. B consumed in NATIVE layout via
// broadcast LDS.128; x staged XOR-swizzled. 4-stage cp.async pipeline
// (prefetch depth 3), one barrier per tile. occ 4 (32 warps/SM).
__global__ void __launch_bounds__(256, 4) lora_xb(const float* __restrict__ x,
                                                  const float* __restrict__ B) {
    __shared__ float xs[XB_STAGES][XB_ROWS][XB_AT];   // 4 x 8 KB
    __shared__ float bs[XB_STAGES][XB_AT][R_DIM];     // 4 x 2 KB

    const int tid   = threadIdx.x;
    const int wid   = tid >> 5;
    const int lane  = tid & 31;
    const int row0  = (blockIdx.x >> 2) * XB_ROWS;
    const int split = blockIdx.x & 3;
    const int i0    = split * XB_ISPAN;

    const float4* xg = reinterpret_cast<const float4*>(x);
    const float4* Bg = reinterpret_cast<const float4*>(B);   // B row i = 4 float4

    auto stage = [&](int it, int buf) {
        float4* xs4 = reinterpret_cast<float4*>(&xs[buf][0][0]);   // [64][8]
        float4* bs4 = reinterpret_cast<float4*>(&bs[buf][0][0]);   // [128]
        // x: 64 rows x 8 float4 = 512 -> 2 per thread, XOR-swizzled dst
#pragma unroll
        for (int k = 0; k < 2; k++) {
            int f  = tid + k * 256;
            int rw = f >> 3;          // 0..63
            int c4 = f & 7;           // 0..7
            cp16(s2u(&xs4[rw * 8 + (c4 ^ (rw & 7))]),
                 &xg[(size_t)(row0 + rw) * (IN_DIM / 4) + (i0 >> 2) + it * (XB_AT / 4) + c4]);
        }
        // B tile: 32 rows x 4 float4 = 128 contiguous -> threads 0..127
        if (tid < 128)
            cp16(s2u(&bs4[tid]), &Bg[(size_t)(i0 + it * XB_AT) * 4 + tid]);
        CP_COMMIT();
    };

    stage(0, 0);
    stage(1, 1);
    stage(2, 2);

    u64 acc[2][8];
#pragma unroll
    for (int s = 0; s < 2; s++)
#pragma unroll
        for (int j = 0; j < 8; j++) acc[s][j] = 0ull;

    for (int it = 0; it < XB_NT; it++) {
        const int buf = it % XB_STAGES;
        if      (it <= XB_NT - 3) { CP_WAIT(2); }
        else if (it == XB_NT - 2) { CP_WAIT(1); }
        else                      { CP_WAIT(0); }
        __syncthreads();   // tile `it` visible; buf (it+3)%4 free to restage
        if (it + 3 < XB_NT) stage(it + 3, (it + 3) % XB_STAGES);

        const float4*     xs4 = reinterpret_cast<const float4*>(&xs[buf][0][0]);
        const ulonglong2* bs2 = reinterpret_cast<const ulonglong2*>(&bs[buf][0][0]);

        // warp's i-slice: [wid*4, wid*4+4) = one float4 per row
        float4 xq0 = xs4[lane * 8 + (wid ^ (lane & 7))];
        float4 xq1 = xs4[(lane + 32) * 8 + (wid ^ (lane & 7))];
        float xe0[4] = {xq0.x, xq0.y, xq0.z, xq0.w};
        float xe1[4] = {xq1.x, xq1.y, xq1.z, xq1.w};
#pragma unroll
        for (int e = 0; e < 4; e++) {
            const int il = wid * 4 + e;            // i within tile
            ulonglong2 b01 = bs2[il * 4 + 0];      // broadcast: r0..3
            ulonglong2 b23 = bs2[il * 4 + 1];      // r4..7
            ulonglong2 b45 = bs2[il * 4 + 2];      // r8..11
            ulonglong2 b67 = bs2[il * 4 + 3];      // r12..15
            u64 xx0 = pack2(xe0[e], xe0[e]);
            u64 xx1 = pack2(xe1[e], xe1[e]);
            ffma2(acc[0][0], xx0, b01.x);
            ffma2(acc[0][1], xx0, b01.y);
            ffma2(acc[0][2], xx0, b23.x);
            ffma2(acc[0][3], xx0, b23.y);
            ffma2(acc[0][4], xx0, b45.x);
            ffma2(acc[0][5], xx0, b45.y);
            ffma2(acc[0][6], xx0, b67.x);
            ffma2(acc[0][7], xx0, b67.y);
            ffma2(acc[1][0], xx1, b01.x);
            ffma2(acc[1][1], xx1, b01.y);
            ffma2(acc[1][2], xx1, b23.x);
            ffma2(acc[1][3], xx1, b23.y);
            ffma2(acc[1][4], xx1, b45.x);
            ffma2(acc[1][5], xx1, b45.y);
            ffma2(acc[1][6], xx1, b67.x);
            ffma2(acc[1][7], xx1, b67.y);
        }
    }
    __syncthreads();   // all compute done before reusing xs for reduction

    // cross-warp reduction through smem (reuse xs: 256 thr * 16 u64 = 32 KB)
    u64* red = reinterpret_cast<u64*>(&xs[0][0][0]);
#pragma unroll
    for (int s = 0; s < 2; s++)
#pragma unroll
        for (int j = 0; j < 8; j++)
            red[(wid * 32 + lane) * 16 + s * 8 + j] = acc[s][j];
    __syncthreads();

#pragma unroll
    for (int k = 0; k < 2; k++) {
        const int item = tid + k * 256;    // 0..511 -> (row, slot)
        const int row  = item >> 3;        // 0..63
        const int slot = item & 7;
        const int lrow = row & 31;
        const int rsel = row >> 5;
        u64 s = red[(0 * 32 + lrow) * 16 + rsel * 8 + slot];
#pragma unroll
        for (int w = 1; w < 8; w++)
            addf2(s, s, red[(w * 32 + lrow) * 16 + rsel * 8 + slot]);
        u64 two = pack2(2.0f, 2.0f);       // LoRA scale folded here
        mulf2(s, s, two);
        g_xbp[split][row0 + row][slot] = s;
    }
}

// ---------- kernel B: out = xb @ A (R4 design, proven 30.6us) ----------
// 128 threads; block covers 64 rows x 512 cols. A slice (16 r x 1 ulonglong2
// = 64 regs) in regs; xb (sum of 4 splits) broadcast from smem. Grid 1024.
#define O_ROWS 64

__global__ void __launch_bounds__(128, 4) lora_out(const float* __restrict__ A,
                                                   float* __restrict__ out) {
    __shared__ u64 xbs[O_ROWS * R_DIM];   // 8 KB, entries packed (v,v)

    const int tid    = threadIdx.x;
    const int rowblk = blockIdx.x >> 3;
    const int colblk = blockIdx.x & 7;
    const int row0   = rowblk * O_ROWS;

    // fill xbs: 64 rows * 8 u64-slots = 512 -> 4 per thread; sum the 4 splits
    {
        const u64* gp = &g_xbp[0][row0][0];
        const size_t sstr = (size_t)ROWS_TOTAL * (R_DIM / 2);
#pragma unroll
        for (int k = 0; k < 4; k++) {
            int j = tid + k * 128;            // j -> (row = j>>3, slot = j&7)
            u64 p01, p23;
            addf2(p01, gp[j], gp[sstr + j]);
            addf2(p23, gp[2 * sstr + j], gp[3 * sstr + j]);
            u64 p;
            addf2(p, p01, p23);
            float f0, f1;
            unpack2(p, f0, f1);
            int rw = j >> 3, slot = j & 7;
            xbs[rw * R_DIM + slot * 2 + 0] = pack2(f0, f0);
            xbs[rw * R_DIM + slot * 2 + 1] = pack2(f1, f1);
        }
    }
    __syncthreads();

    // A slice into registers: 16 r x 1 ulonglong2 (4 cols), coalesced
    const ulonglong2* Av = reinterpret_cast<const ulonglong2*>(A);  // [16][1024]
    const int cu = colblk * 128 + tid;    // ulonglong2 index within a row
    ulonglong2 Ar[R_DIM];
#pragma unroll
    for (int rr = 0; rr < R_DIM; rr++)
        Ar[rr] = Av[(size_t)rr * (OUT_DIM / 4) + cu];

    ulonglong2* outv = reinterpret_cast<ulonglong2*>(out);
    const ulonglong2* xu = reinterpret_cast<const ulonglong2*>(xbs);

#pragma unroll 2
    for (int rw = 0; rw < O_ROWS; rw++) {
        u64 a0e = 0ull, a0o = 0ull, a1e = 0ull, a1o = 0ull;
#pragma unroll
        for (int q = 0; q < 8; q++) {
            ulonglong2 xq = xu[rw * 8 + q];   // bcast (xb_2q,xb_2q),(xb_2q+1,..)
            ffma2(a0e, xq.x, Ar[2 * q].x);
            ffma2(a1e, xq.x, Ar[2 * q].y);
            ffma2(a0o, xq.y, Ar[2 * q + 1].x);
            ffma2(a1o, xq.y, Ar[2 * q + 1].y);
        }
        u64 o0, o1;
        addf2(o0, a0e, a0o);
        addf2(o1, a1e, a1o);
        ulonglong2 v; v.x = o0; v.y = o1;
        outv[(size_t)(row0 + rw) * (OUT_DIM / 4) + cu] = v;   // STG.128 coalesced
    }
}

// ---------- launch ----------
extern "C" void kernel_launch(void* const* d_in, const int* in_sizes, int n_in,
                              void* d_out, int out_size) {
    const float* x  = (const float*)d_in[0];   // [4, 2048, 4096]
    const float* lA = (const float*)d_in[1];   // [16, 4096]
    const float* lB = (const float*)d_in[2];   // [4096, 16]
    float* out = (float*)d_out;

    lora_xb<<<(ROWS_TOTAL / XB_ROWS) * XB_SPLIT, 256>>>(x, lB);          // 512
    lora_out<<<(ROWS_TOTAL / O_ROWS) * (OUT_DIM / 512), 128>>>(lA, out); // 1024
}

// round 14
// speedup vs baseline: 1.6701x; 1.1133x over previous
#include <cuda_runtime.h>
#include <cstdint>

// LoRA forward: out = (x @ B) @ A * 2
//   x: [8192, 4096] fp32, B: [4096, 16], A: [16, 4096], out: [8192, 4096]
//  lora_xb : R7/R11 pipeline at occ 3, i-split x8 (grid 1024) to kill the
//            2-wave quantization that capped it at ~41us.
//  lora_out: R4 config EXACTLY (proven ~30us), prologue sums 8 partials.

#define ROWS_TOTAL 8192
#define IN_DIM     4096
#define OUT_DIM    4096
#define R_DIM      16

#define XB_SPLIT   8
#define XB_ISPAN   (IN_DIM / XB_SPLIT)     // 512 i per block
#define XB_AT      32                       // i per tile
#define XB_NT      (XB_ISPAN / XB_AT)       // 16 tiles
#define XB_ROWS    64                       // rows per block (2 per lane)
#define XB_STAGES  4

typedef unsigned long long u64;

// partial xb: [split][row][8] u64, each u64 = (xb_{2j}, xb_{2j+1}), scaled by 2
__device__ u64 g_xbp[XB_SPLIT][ROWS_TOTAL][R_DIM / 2];

// ---------- packed f32x2 helpers ----------
__device__ __forceinline__ u64 pack2(float lo, float hi) {
    u64 r; asm("mov.b64 %0, {%1, %2};" : "=l"(r) : "f"(lo), "f"(hi)); return r;
}
__device__ __forceinline__ void unpack2(u64 v, float& lo, float& hi) {
    asm("mov.b64 {%0, %1}, %2;" : "=f"(lo), "=f"(hi) : "l"(v));
}
__device__ __forceinline__ void ffma2(u64& d, u64 a, u64 b) {
    asm("fma.rn.f32x2 %0, %1, %2, %0;" : "+l"(d) : "l"(a), "l"(b));
}
__device__ __forceinline__ void addf2(u64& d, u64 a, u64 b) {
    asm("add.rn.f32x2 %0, %1, %2;" : "=l"(d) : "l"(a), "l"(b));
}
__device__ __forceinline__ void mulf2(u64& d, u64 a, u64 b) {
    asm("mul.rn.f32x2 %0, %1, %2;" : "=l"(d) : "l"(a), "l"(b));
}

// ---------- cp.async helpers ----------
__device__ __forceinline__ uint32_t s2u(const void* p) {
    return (uint32_t)__cvta_generic_to_shared(p);
}
__device__ __forceinline__ void cp16(uint32_t dst, const void* src) {
    asm volatile("cp.async.cg.shared.global [%0], [%1], 16;"
                 :: "r"(dst), "l"(src) : "memory");
}
#define CP_COMMIT()  asm volatile("cp.async.commit_group;" ::: "memory")
#define CP_WAIT(N)   asm volatile("cp.async.wait_group %0;" :: "n"(N) : "memory")

// ---------- kernel A: partial xb ----------
// 256 threads = 8 warps; lane covers rows {lane, lane+32}. Warp w covers
// i-subrange [w*4, w*4+4) of each 32-i tile. B consumed in NATIVE layout via
// broadcast LDS.128; x staged XOR-swizzled. 4-stage cp.async pipeline
// (prefetch depth 3), one barrier per tile. occ 3 (84-reg cap, no spill).
__global__ void __launch_bounds__(256, 3) lora_xb(const float* __restrict__ x,
                                                  const float* __restrict__ B) {
    __shared__ float xs[XB_STAGES][XB_ROWS][XB_AT];   // 4 x 8 KB
    __shared__ float bs[XB_STAGES][XB_AT][R_DIM];     // 4 x 2 KB

    const int tid   = threadIdx.x;
    const int wid   = tid >> 5;
    const int lane  = tid & 31;
    const int row0  = (blockIdx.x >> 3) * XB_ROWS;
    const int split = blockIdx.x & 7;
    const int i0    = split * XB_ISPAN;

    const float4* xg = reinterpret_cast<const float4*>(x);
    const float4* Bg = reinterpret_cast<const float4*>(B);   // B row i = 4 float4

    auto stage = [&](int it, int buf) {
        float4* xs4 = reinterpret_cast<float4*>(&xs[buf][0][0]);   // [64][8]
        float4* bs4 = reinterpret_cast<float4*>(&bs[buf][0][0]);   // [128]
        // x: 64 rows x 8 float4 = 512 -> 2 per thread, XOR-swizzled dst
#pragma unroll
        for (int k = 0; k < 2; k++) {
            int f  = tid + k * 256;
            int rw = f >> 3;          // 0..63
            int c4 = f & 7;           // 0..7
            cp16(s2u(&xs4[rw * 8 + (c4 ^ (rw & 7))]),
                 &xg[(size_t)(row0 + rw) * (IN_DIM / 4) + (i0 >> 2) + it * (XB_AT / 4) + c4]);
        }
        // B tile: 32 rows x 4 float4 = 128 contiguous -> threads 0..127
        if (tid < 128)
            cp16(s2u(&bs4[tid]), &Bg[(size_t)(i0 + it * XB_AT) * 4 + tid]);
        CP_COMMIT();
    };

    stage(0, 0);
    stage(1, 1);
    stage(2, 2);

    u64 acc[2][8];
#pragma unroll
    for (int s = 0; s < 2; s++)
#pragma unroll
        for (int j = 0; j < 8; j++) acc[s][j] = 0ull;

    for (int it = 0; it < XB_NT; it++) {
        const int buf = it % XB_STAGES;
        if      (it <= XB_NT - 3) { CP_WAIT(2); }
        else if (it == XB_NT - 2) { CP_WAIT(1); }
        else                      { CP_WAIT(0); }
        __syncthreads();   // tile `it` visible; buf (it+3)%4 free to restage
        if (it + 3 < XB_NT) stage(it + 3, (it + 3) % XB_STAGES);

        const float4*     xs4 = reinterpret_cast<const float4*>(&xs[buf][0][0]);
        const ulonglong2* bs2 = reinterpret_cast<const ulonglong2*>(&bs[buf][0][0]);

        // warp's i-slice: [wid*4, wid*4+4) = one float4 per row
        float4 xq0 = xs4[lane * 8 + (wid ^ (lane & 7))];
        float4 xq1 = xs4[(lane + 32) * 8 + (wid ^ (lane & 7))];
        float xe0[4] = {xq0.x, xq0.y, xq0.z, xq0.w};
        float xe1[4] = {xq1.x, xq1.y, xq1.z, xq1.w};
#pragma unroll
        for (int e = 0; e < 4; e++) {
            const int il = wid * 4 + e;            // i within tile
            ulonglong2 b01 = bs2[il * 4 + 0];      // broadcast: r0..3
            ulonglong2 b23 = bs2[il * 4 + 1];      // r4..7
            ulonglong2 b45 = bs2[il * 4 + 2];      // r8..11
            ulonglong2 b67 = bs2[il * 4 + 3];      // r12..15
            u64 xx0 = pack2(xe0[e], xe0[e]);
            u64 xx1 = pack2(xe1[e], xe1[e]);
            ffma2(acc[0][0], xx0, b01.x);
            ffma2(acc[0][1], xx0, b01.y);
            ffma2(acc[0][2], xx0, b23.x);
            ffma2(acc[0][3], xx0, b23.y);
            ffma2(acc[0][4], xx0, b45.x);
            ffma2(acc[0][5], xx0, b45.y);
            ffma2(acc[0][6], xx0, b67.x);
            ffma2(acc[0][7], xx0, b67.y);
            ffma2(acc[1][0], xx1, b01.x);
            ffma2(acc[1][1], xx1, b01.y);
            ffma2(acc[1][2], xx1, b23.x);
            ffma2(acc[1][3], xx1, b23.y);
            ffma2(acc[1][4], xx1, b45.x);
            ffma2(acc[1][5], xx1, b45.y);
            ffma2(acc[1][6], xx1, b67.x);
            ffma2(acc[1][7], xx1, b67.y);
        }
    }
    __syncthreads();   // all compute done before reusing xs for reduction

    // cross-warp reduction through smem (reuse xs: 256 thr * 16 u64 = 32 KB)
    u64* red = reinterpret_cast<u64*>(&xs[0][0][0]);
#pragma unroll
    for (int s = 0; s < 2; s++)
#pragma unroll
        for (int j = 0; j < 8; j++)
            red[(wid * 32 + lane) * 16 + s * 8 + j] = acc[s][j];
    __syncthreads();

#pragma unroll
    for (int k = 0; k < 2; k++) {
        const int item = tid + k * 256;    // 0..511 -> (row, slot)
        const int row  = item >> 3;        // 0..63
        const int slot = item & 7;
        const int lrow = row & 31;
        const int rsel = row >> 5;
        u64 s = red[(0 * 32 + lrow) * 16 + rsel * 8 + slot];
#pragma unroll
        for (int w = 1; w < 8; w++)
            addf2(s, s, red[(w * 32 + lrow) * 16 + rsel * 8 + slot]);
        u64 two = pack2(2.0f, 2.0f);       // LoRA scale folded here
        mulf2(s, s, two);
        g_xbp[split][row0 + row][slot] = s;
    }
}

// ---------- kernel B: out = xb @ A (R4 design, proven ~30us) ----------
// 128 threads; block covers 64 rows x 512 cols. A slice (16 r x 1 ulonglong2)
// in regs; xb (sum of 8 splits) broadcast from smem. Grid 1024.
#define O_ROWS 64

__global__ void __launch_bounds__(128, 4) lora_out(const float* __restrict__ A,
                                                   float* __restrict__ out) {
    __shared__ u64 xbs[O_ROWS * R_DIM];   // 8 KB, entries packed (v,v)

    const int tid    = threadIdx.x;
    const int rowblk = blockIdx.x >> 3;
    const int colblk = blockIdx.x & 7;
    const int row0   = rowblk * O_ROWS;

    // fill xbs: 64 rows * 8 u64-slots = 512 -> 4 per thread; sum the 8 splits
    {
        const u64* gp = &g_xbp[0][row0][0];
        const size_t sstr = (size_t)ROWS_TOTAL * (R_DIM / 2);
#pragma unroll
        for (int k = 0; k < 4; k++) {
            int j = tid + k * 128;            // j -> (row = j>>3, slot = j&7)
            u64 s0, s1, s2, s3;
            addf2(s0, gp[0 * sstr + j], gp[1 * sstr + j]);
            addf2(s1, gp[2 * sstr + j], gp[3 * sstr + j]);
            addf2(s2, gp[4 * sstr + j], gp[5 * sstr + j]);
            addf2(s3, gp[6 * sstr + j], gp[7 * sstr + j]);
            addf2(s0, s0, s1);
            addf2(s2, s2, s3);
            addf2(s0, s0, s2);
            float f0, f1;
            unpack2(s0, f0, f1);
            int rw = j >> 3, slot = j & 7;
            xbs[rw * R_DIM + slot * 2 + 0] = pack2(f0, f0);
            xbs[rw * R_DIM + slot * 2 + 1] = pack2(f1, f1);
        }
    }
    __syncthreads();

    // A slice into registers: 16 r x 1 ulonglong2 (4 cols), coalesced
    const ulonglong2* Av = reinterpret_cast<const ulonglong2*>(A);  // [16][1024]
    const int cu = colblk * 128 + tid;    // ulonglong2 index within a row
    ulonglong2 Ar[R_DIM];
#pragma unroll
    for (int rr = 0; rr < R_DIM; rr++)
        Ar[rr] = Av[(size_t)rr * (OUT_DIM / 4) + cu];

    ulonglong2* outv = reinterpret_cast<ulonglong2*>(out);
    const ulonglong2* xu = reinterpret_cast<const ulonglong2*>(xbs);

#pragma unroll 2
    for (int rw = 0; rw < O_ROWS; rw++) {
        u64 a0e = 0ull, a0o = 0ull, a1e = 0ull, a1o = 0ull;
#pragma unroll
        for (int q = 0; q < 8; q++) {
            ulonglong2 xq = xu[rw * 8 + q];   // bcast (xb_2q,xb_2q),(xb_2q+1,..)
            ffma2(a0e, xq.x, Ar[2 * q].x);
            ffma2(a1e, xq.x, Ar[2 * q].y);
            ffma2(a0o, xq.y, Ar[2 * q + 1].x);
            ffma2(a1o, xq.y, Ar[2 * q + 1].y);
        }
        u64 o0, o1;
        addf2(o0, a0e, a0o);
        addf2(o1, a1e, a1o);
        ulonglong2 v; v.x = o0; v.y = o1;
        outv[(size_t)(row0 + rw) * (OUT_DIM / 4) + cu] = v;   // STG.128 coalesced
    }
}

// ---------- launch ----------
extern "C" void kernel_launch(void* const* d_in, const int* in_sizes, int n_in,
                              void* d_out, int out_size) {
    const float* x  = (const float*)d_in[0];   // [4, 2048, 4096]
    const float* lA = (const float*)d_in[1];   // [16, 4096]
    const float* lB = (const float*)d_in[2];   // [4096, 16]
    float* out = (float*)d_out;

    lora_xb<<<(ROWS_TOTAL / XB_ROWS) * XB_SPLIT, 256>>>(x, lB);          // 1024
    lora_out<<<(ROWS_TOTAL / O_ROWS) * (OUT_DIM / 512), 128>>>(lA, out); // 1024
}